// round 2
// baseline (speedup 1.0000x reference)
#include <cuda_runtime.h>

// Shapes are fixed by the problem: B=16, P=12, N=2048, H=64, E=16384, Q=P.
#define BB 16
#define PP 12
#define NN 2048
#define HH 64
#define NH (NN*HH)          // 131072
#define BPc (BB*PP)         // 192
#define EE 16384
#define EPSV 1e-5f

// -------- scratch in __device__ globals (no allocations allowed) ----------
__device__ float  g_y[BB*PP*NN*HH];      // ~100.7 MB intermediate after graph conv
__device__ float2 g_stats1[BPc];         // (mean, rstd) for LN1
__device__ float2 g_part1[BPc*4];
__device__ float2 g_part2[BPc*256];
__device__ float2 g_stats2[BPc];         // (mean, rstd) for LN2
__device__ int    g_deg[NN];
__device__ float  g_dinv[NN];
__device__ int    g_rowptr[NN+1];
__device__ int    g_cursor[NN];
__device__ int    g_bucket[EE];
__device__ int    g_srcS[EE];
__device__ float  g_normS[EE];
__device__ int    g_is64;

// -------- edge dtype detection (jax may emit int32 despite jnp.int64) -----
__global__ void k_detect(const void* __restrict__ ei) {
    // First 32 int64 interpretations: if the buffer is really int32 pairs,
    // the high word is a dst/src value (almost surely nonzero) -> huge int64.
    long long v = ((const long long*)ei)[threadIdx.x];
    int ok = (v >= 0 && v < (long long)NN);
    unsigned m = __ballot_sync(0xffffffffu, ok);
    if (threadIdx.x == 0) g_is64 = (m == 0xffffffffu) ? 1 : 0;
}

__device__ __forceinline__ int edge_val(const void* ei, int idx, int is64) {
    return is64 ? (int)((const long long*)ei)[idx] : ((const int*)ei)[idx];
}

// -------- CSR build -------------------------------------------------------
__global__ void k_zero() {
    int i = blockIdx.x * blockDim.x + threadIdx.x;
    if (i < NN) { g_deg[i] = 0; g_cursor[i] = 0; }
}

__global__ void k_count(const void* __restrict__ ei) {
    int e = blockIdx.x * blockDim.x + threadIdx.x;
    if (e >= EE) return;
    int d = edge_val(ei, EE + e, g_is64);
    atomicAdd(&g_deg[d], 1);
}

__global__ void k_scan() {   // 1 block, 1024 threads: exclusive scan of deg[2048]
    __shared__ int sh[1024];
    int t = threadIdx.x;
    int a = g_deg[2*t], b = g_deg[2*t+1];
    sh[t] = a + b;
    __syncthreads();
    for (int off = 1; off < 1024; off <<= 1) {
        int v = (t >= off) ? sh[t - off] : 0;
        __syncthreads();
        sh[t] += v;
        __syncthreads();
    }
    int excl = (t > 0) ? sh[t-1] : 0;
    g_rowptr[2*t]   = excl;
    g_rowptr[2*t+1] = excl + a;
    if (t == 1023) g_rowptr[NN] = sh[1023];
    g_dinv[2*t]   = (a > 0) ? rsqrtf((float)a) : 0.f;
    g_dinv[2*t+1] = (b > 0) ? rsqrtf((float)b) : 0.f;
}

__global__ void k_scatter(const void* __restrict__ ei) {
    int e = blockIdx.x * blockDim.x + threadIdx.x;
    if (e >= EE) return;
    int is64 = g_is64;
    int d = edge_val(ei, EE + e, is64);
    int pos = g_rowptr[d] + atomicAdd(&g_cursor[d], 1);
    g_bucket[pos] = e;
}

// Sort each node's bucket by edge id -> deterministic accumulation order,
// then precompute (src, norm) per sorted slot.
__global__ void k_sortfill(const void* __restrict__ ei) {
    int n = blockIdx.x * blockDim.x + threadIdx.x;
    if (n >= NN) return;
    int beg = g_rowptr[n], end = g_rowptr[n+1];
    for (int i = beg + 1; i < end; i++) {        // tiny buckets (avg 8)
        int key = g_bucket[i]; int j = i - 1;
        while (j >= beg && g_bucket[j] > key) { g_bucket[j+1] = g_bucket[j]; j--; }
        g_bucket[j+1] = key;
    }
    int is64 = g_is64;
    float dn = g_dinv[n];
    for (int i = beg; i < end; i++) {
        int e = g_bucket[i];
        int s = edge_val(ei, e, is64);
        g_srcS[i]  = s;
        g_normS[i] = g_dinv[s] * dn;
    }
}

// -------- LN1 stats -------------------------------------------------------
__global__ void k_stats1(const float4* __restrict__ x4) {
    int bp = blockIdx.y, ch = blockIdx.x, t = threadIdx.x;
    int base = bp * (NH/4) + ch * 8192;          // quarter slice = 8192 float4
    float s = 0.f, q = 0.f;
    #pragma unroll
    for (int i = 0; i < 32; i++) {
        float4 v = x4[base + i*256 + t];
        s += v.x + v.y + v.z + v.w;
        q += v.x*v.x + v.y*v.y + v.z*v.z + v.w*v.w;
    }
    __shared__ float ss[256], sq[256];
    ss[t] = s; sq[t] = q; __syncthreads();
    for (int off = 128; off > 0; off >>= 1) {
        if (t < off) { ss[t] += ss[t+off]; sq[t] += sq[t+off]; }
        __syncthreads();
    }
    if (t == 0) g_part1[bp*4 + ch] = make_float2(ss[0], sq[0]);
}

__global__ void k_stats1b() {
    int bp = threadIdx.x;
    if (bp >= BPc) return;
    float s = 0.f, q = 0.f;
    for (int i = 0; i < 4; i++) { float2 v = g_part1[bp*4+i]; s += v.x; q += v.y; }
    float mean = s / (float)NH;
    float var  = q / (float)NH - mean * mean;
    g_stats1[bp] = make_float2(mean, rsqrtf(var + EPSV));
}

// -------- fused LN1 + LightGCN gather-accumulate + LN2 partial stats ------
__global__ void k_conv(const float* __restrict__ x,
                       const float* __restrict__ gw,
                       const float* __restrict__ gb) {
    int bp   = blockIdx.y;
    int w    = threadIdx.x >> 5;
    int lane = threadIdx.x & 31;
    int n    = blockIdx.x * 8 + w;               // one warp per node
    float2 st = g_stats1[bp];
    float m = st.x, r = st.y;
    const float* xs = x + bp * NH;
    int beg = g_rowptr[n], end = g_rowptr[n+1];
    int h = lane * 2;
    float2 acc = make_float2(0.f, 0.f);
    for (int i = beg; i < end; i++) {
        int   s   = g_srcS[i];
        float nrm = g_normS[i];
        float2 xv  = *(const float2*)(xs + s*HH + h);
        float2 gwv = *(const float2*)(gw + s*HH + h);
        float2 gbv = *(const float2*)(gb + s*HH + h);
        float v0 = fmaf((xv.x - m) * r, gwv.x, gbv.x);
        float v1 = fmaf((xv.y - m) * r, gwv.y, gbv.y);
        acc.x = fmaf(nrm, v0, acc.x);
        acc.y = fmaf(nrm, v1, acc.y);
    }
    *(float2*)(g_y + bp*NH + n*HH + h) = acc;

    // LN2 partial stats: fixed-order warp + block reduction (deterministic)
    float s1 = acc.x + acc.y;
    float q1 = acc.x*acc.x + acc.y*acc.y;
    for (int off = 16; off > 0; off >>= 1) {
        s1 += __shfl_down_sync(0xffffffffu, s1, off);
        q1 += __shfl_down_sync(0xffffffffu, q1, off);
    }
    __shared__ float ssum[8], ssq[8];
    if (lane == 0) { ssum[w] = s1; ssq[w] = q1; }
    __syncthreads();
    if (threadIdx.x == 0) {
        float s = 0.f, q = 0.f;
        for (int i = 0; i < 8; i++) { s += ssum[i]; q += ssq[i]; }
        g_part2[bp*256 + blockIdx.x] = make_float2(s, q);
    }
}

__global__ void k_stats2() {
    int bp = blockIdx.x, t = threadIdx.x;
    float2 v = g_part2[bp*256 + t];
    __shared__ float ss[256], sq[256];
    ss[t] = v.x; sq[t] = v.y; __syncthreads();
    for (int off = 128; off > 0; off >>= 1) {
        if (t < off) { ss[t] += ss[t+off]; sq[t] += sq[t+off]; }
        __syncthreads();
    }
    if (t == 0) {
        float mean = ss[0] / (float)NH;
        float var  = sq[0] / (float)NH - mean * mean;
        g_stats2[bp] = make_float2(mean, rsqrtf(var + EPSV));
    }
}

// -------- fused LN2 + 1x1 conv over periods + bias ------------------------
__global__ void k_out(const float* __restrict__ tw,
                      const float* __restrict__ tb,
                      const float* __restrict__ cw,
                      const float* __restrict__ cb,
                      float* __restrict__ out) {
    __shared__ float  scw[144], srow[12], scb[12];
    __shared__ float2 sst[12];
    int t   = threadIdx.x;
    int gid = blockIdx.x * 256 + t;
    int b   = gid >> 16;                 // 65536 (n,h2) positions per batch
    if (t < 144)              scw[t]      = cw[t];
    if (t >= 144 && t < 156)  scb[t-144]  = cb[t-144];
    if (t >= 160 && t < 172)  sst[t-160]  = g_stats2[b*PP + (t-160)];
    __syncthreads();
    if (t < 12) {
        float s = 0.f;
        for (int p = 0; p < 12; p++) s += scw[t*12 + p];
        srow[t] = s;
    }
    __syncthreads();

    int h2 = gid & 31;
    int n  = (gid >> 5) & 2047;
    int h  = h2 * 2;

    float2 tv[12];
    #pragma unroll
    for (int p = 0; p < 12; p++) {
        float2 yv = *(const float2*)(g_y + ((b*PP + p)*NN + n)*HH + h);
        float2 st = sst[p];
        tv[p].x = (yv.x - st.x) * st.y;
        tv[p].y = (yv.y - st.x) * st.y;
    }
    float2 tw2 = *(const float2*)(tw + n*HH + h);
    float2 tb2 = *(const float2*)(tb + n*HH + h);

    #pragma unroll
    for (int q = 0; q < 12; q++) {
        float ax = 0.f, ay = 0.f;
        #pragma unroll
        for (int p = 0; p < 12; p++) {
            float c = scw[q*12 + p];
            ax = fmaf(c, tv[p].x, ax);
            ay = fmaf(c, tv[p].y, ay);
        }
        // out = tw * sum_p(c*t_p) + tb * rowsum[q] + cb[q]
        float ox = fmaf(tw2.x, ax, fmaf(tb2.x, srow[q], scb[q]));
        float oy = fmaf(tw2.y, ay, fmaf(tb2.y, srow[q], scb[q]));
        *(float2*)(out + ((b*PP + q)*NN + n)*HH + h) = make_float2(ox, oy);
    }
}

// --------------------------------------------------------------------------
extern "C" void kernel_launch(void* const* d_in, const int* in_sizes, int n_in,
                              void* d_out, int out_size) {
    const float* x  = (const float*)d_in[0];
    const void*  ei = d_in[1];
    const float* gw = (const float*)d_in[2];
    const float* gb = (const float*)d_in[3];
    const float* tw = (const float*)d_in[4];
    const float* tb = (const float*)d_in[5];
    const float* cw = (const float*)d_in[6];
    const float* cb = (const float*)d_in[7];
    float* out = (float*)d_out;

    k_detect  <<<1, 32>>>(ei);
    k_zero    <<<8, 256>>>();
    k_count   <<<64, 256>>>(ei);
    k_scan    <<<1, 1024>>>();
    k_scatter <<<64, 256>>>(ei);
    k_sortfill<<<8, 256>>>(ei);
    k_stats1  <<<dim3(4, BPc), 256>>>((const float4*)x);
    k_stats1b <<<1, 256>>>();
    k_conv    <<<dim3(NN/8, BPc), 256>>>(x, gw, gb);
    k_stats2  <<<BPc, 256>>>();
    k_out     <<<4096, 256>>>(tw, tb, cw, cb, out);
}

// round 3
// speedup vs baseline: 1.0081x; 1.0081x over previous
#include <cuda_runtime.h>

// Shapes are fixed by the problem: B=16, P=12, N=2048, H=64, E=16384, Q=P.
#define BB 16
#define PP 12
#define NN 2048
#define HH 64
#define NH (NN*HH)          // 131072
#define BPc (BB*PP)         // 192
#define EE 16384
#define EPSV 1e-5f

// -------- scratch in __device__ globals (no allocations allowed) ----------
__device__ float  g_y[BB*PP*NN*HH];      // ~100.7 MB intermediate after graph conv
__device__ float2 g_stats1[BPc];         // (mean, rstd) for LN1
__device__ float2 g_part1[BPc*4];
__device__ float2 g_part2[BPc*256];
__device__ float2 g_stats2[BPc];         // (mean, rstd) for LN2
__device__ int    g_deg[NN];
__device__ float  g_dinv[NN];
__device__ int    g_rowptr[NN+1];
__device__ int    g_cursor[NN];
__device__ int    g_bucket[EE];
__device__ int    g_srcS[EE];
__device__ float  g_normS[EE];
__device__ int    g_is64;

// -------- edge dtype detection (jax may emit int32 despite jnp.int64) -----
__global__ void k_detect(const void* __restrict__ ei) {
    // First 32 int64 interpretations: if the buffer is really int32 pairs,
    // the high word is a dst/src value (almost surely nonzero) -> huge int64.
    long long v = ((const long long*)ei)[threadIdx.x];
    int ok = (v >= 0 && v < (long long)NN);
    unsigned m = __ballot_sync(0xffffffffu, ok);
    if (threadIdx.x == 0) g_is64 = (m == 0xffffffffu) ? 1 : 0;
}

__device__ __forceinline__ int edge_val(const void* ei, int idx, int is64) {
    return is64 ? (int)((const long long*)ei)[idx] : ((const int*)ei)[idx];
}

// -------- CSR build -------------------------------------------------------
__global__ void k_zero() {
    int i = blockIdx.x * blockDim.x + threadIdx.x;
    if (i < NN) { g_deg[i] = 0; g_cursor[i] = 0; }
}

__global__ void k_count(const void* __restrict__ ei) {
    int e = blockIdx.x * blockDim.x + threadIdx.x;
    if (e >= EE) return;
    int d = edge_val(ei, EE + e, g_is64);
    atomicAdd(&g_deg[d], 1);
}

__global__ void k_scan() {   // 1 block, 1024 threads: exclusive scan of deg[2048]
    __shared__ int sh[1024];
    int t = threadIdx.x;
    int a = g_deg[2*t], b = g_deg[2*t+1];
    sh[t] = a + b;
    __syncthreads();
    for (int off = 1; off < 1024; off <<= 1) {
        int v = (t >= off) ? sh[t - off] : 0;
        __syncthreads();
        sh[t] += v;
        __syncthreads();
    }
    int excl = (t > 0) ? sh[t-1] : 0;
    g_rowptr[2*t]   = excl;
    g_rowptr[2*t+1] = excl + a;
    if (t == 1023) g_rowptr[NN] = sh[1023];
    g_dinv[2*t]   = (a > 0) ? rsqrtf((float)a) : 0.f;
    g_dinv[2*t+1] = (b > 0) ? rsqrtf((float)b) : 0.f;
}

__global__ void k_scatter(const void* __restrict__ ei) {
    int e = blockIdx.x * blockDim.x + threadIdx.x;
    if (e >= EE) return;
    int is64 = g_is64;
    int d = edge_val(ei, EE + e, is64);
    int pos = g_rowptr[d] + atomicAdd(&g_cursor[d], 1);
    g_bucket[pos] = e;
}

// Sort each node's bucket by edge id -> deterministic accumulation order,
// then precompute (src, norm) per sorted slot.
__global__ void k_sortfill(const void* __restrict__ ei) {
    int n = blockIdx.x * blockDim.x + threadIdx.x;
    if (n >= NN) return;
    int beg = g_rowptr[n], end = g_rowptr[n+1];
    for (int i = beg + 1; i < end; i++) {        // tiny buckets (avg 8)
        int key = g_bucket[i]; int j = i - 1;
        while (j >= beg && g_bucket[j] > key) { g_bucket[j+1] = g_bucket[j]; j--; }
        g_bucket[j+1] = key;
    }
    int is64 = g_is64;
    float dn = g_dinv[n];
    for (int i = beg; i < end; i++) {
        int e = g_bucket[i];
        int s = edge_val(ei, e, is64);
        g_srcS[i]  = s;
        g_normS[i] = g_dinv[s] * dn;
    }
}

// -------- LN1 stats -------------------------------------------------------
__global__ void k_stats1(const float4* __restrict__ x4) {
    int bp = blockIdx.y, ch = blockIdx.x, t = threadIdx.x;
    int base = bp * (NH/4) + ch * 8192;          // quarter slice = 8192 float4
    float s = 0.f, q = 0.f;
    #pragma unroll
    for (int i = 0; i < 32; i++) {
        float4 v = x4[base + i*256 + t];
        s += v.x + v.y + v.z + v.w;
        q += v.x*v.x + v.y*v.y + v.z*v.z + v.w*v.w;
    }
    __shared__ float ss[256], sq[256];
    ss[t] = s; sq[t] = q; __syncthreads();
    for (int off = 128; off > 0; off >>= 1) {
        if (t < off) { ss[t] += ss[t+off]; sq[t] += sq[t+off]; }
        __syncthreads();
    }
    if (t == 0) g_part1[bp*4 + ch] = make_float2(ss[0], sq[0]);
}

__global__ void k_stats1b() {
    int bp = threadIdx.x;
    if (bp >= BPc) return;
    float s = 0.f, q = 0.f;
    for (int i = 0; i < 4; i++) { float2 v = g_part1[bp*4+i]; s += v.x; q += v.y; }
    float mean = s / (float)NH;
    float var  = q / (float)NH - mean * mean;
    g_stats1[bp] = make_float2(mean, rsqrtf(var + EPSV));
}

// -------- fused LN1 + LightGCN gather-accumulate + LN2 partial stats ------
__global__ void k_conv(const float* __restrict__ x,
                       const float* __restrict__ gw,
                       const float* __restrict__ gb) {
    int bp   = blockIdx.y;
    int w    = threadIdx.x >> 5;
    int lane = threadIdx.x & 31;
    int n    = blockIdx.x * 8 + w;               // one warp per node
    float2 st = g_stats1[bp];
    float m = st.x, r = st.y;
    const float* xs = x + bp * NH;
    int beg = g_rowptr[n], end = g_rowptr[n+1];
    int h = lane * 2;
    float2 acc = make_float2(0.f, 0.f);
    for (int i = beg; i < end; i++) {
        int   s   = g_srcS[i];
        float nrm = g_normS[i];
        float2 xv  = *(const float2*)(xs + s*HH + h);
        float2 gwv = *(const float2*)(gw + s*HH + h);
        float2 gbv = *(const float2*)(gb + s*HH + h);
        float v0 = fmaf((xv.x - m) * r, gwv.x, gbv.x);
        float v1 = fmaf((xv.y - m) * r, gwv.y, gbv.y);
        acc.x = fmaf(nrm, v0, acc.x);
        acc.y = fmaf(nrm, v1, acc.y);
    }
    *(float2*)(g_y + bp*NH + n*HH + h) = acc;

    // LN2 partial stats: fixed-order warp + block reduction (deterministic)
    float s1 = acc.x + acc.y;
    float q1 = acc.x*acc.x + acc.y*acc.y;
    for (int off = 16; off > 0; off >>= 1) {
        s1 += __shfl_down_sync(0xffffffffu, s1, off);
        q1 += __shfl_down_sync(0xffffffffu, q1, off);
    }
    __shared__ float ssum[8], ssq[8];
    if (lane == 0) { ssum[w] = s1; ssq[w] = q1; }
    __syncthreads();
    if (threadIdx.x == 0) {
        float s = 0.f, q = 0.f;
        for (int i = 0; i < 8; i++) { s += ssum[i]; q += ssq[i]; }
        g_part2[bp*256 + blockIdx.x] = make_float2(s, q);
    }
}

__global__ void k_stats2() {
    int bp = blockIdx.x, t = threadIdx.x;
    float2 v = g_part2[bp*256 + t];
    __shared__ float ss[256], sq[256];
    ss[t] = v.x; sq[t] = v.y; __syncthreads();
    for (int off = 128; off > 0; off >>= 1) {
        if (t < off) { ss[t] += ss[t+off]; sq[t] += sq[t+off]; }
        __syncthreads();
    }
    if (t == 0) {
        float mean = ss[0] / (float)NH;
        float var  = sq[0] / (float)NH - mean * mean;
        g_stats2[bp] = make_float2(mean, rsqrtf(var + EPSV));
    }
}

// -------- fused LN2 + 1x1 conv over periods + bias ------------------------
__global__ void k_out(const float* __restrict__ tw,
                      const float* __restrict__ tb,
                      const float* __restrict__ cw,
                      const float* __restrict__ cb,
                      float* __restrict__ out) {
    __shared__ float  scw[144], srow[12], scb[12];
    __shared__ float2 sst[12];
    int t   = threadIdx.x;
    int gid = blockIdx.x * 256 + t;
    int b   = gid >> 16;                 // 65536 (n,h2) positions per batch
    if (t < 144)              scw[t]      = cw[t];
    if (t >= 144 && t < 156)  scb[t-144]  = cb[t-144];
    if (t >= 160 && t < 172)  sst[t-160]  = g_stats2[b*PP + (t-160)];
    __syncthreads();
    if (t < 12) {
        float s = 0.f;
        for (int p = 0; p < 12; p++) s += scw[t*12 + p];
        srow[t] = s;
    }
    __syncthreads();

    int h2 = gid & 31;
    int n  = (gid >> 5) & 2047;
    int h  = h2 * 2;

    float2 tv[12];
    #pragma unroll
    for (int p = 0; p < 12; p++) {
        float2 yv = *(const float2*)(g_y + ((b*PP + p)*NN + n)*HH + h);
        float2 st = sst[p];
        tv[p].x = (yv.x - st.x) * st.y;
        tv[p].y = (yv.y - st.x) * st.y;
    }
    float2 tw2 = *(const float2*)(tw + n*HH + h);
    float2 tb2 = *(const float2*)(tb + n*HH + h);

    #pragma unroll
    for (int q = 0; q < 12; q++) {
        float ax = 0.f, ay = 0.f;
        #pragma unroll
        for (int p = 0; p < 12; p++) {
            float c = scw[q*12 + p];
            ax = fmaf(c, tv[p].x, ax);
            ay = fmaf(c, tv[p].y, ay);
        }
        // out = tw * sum_p(c*t_p) + tb * rowsum[q] + cb[q]
        float ox = fmaf(tw2.x, ax, fmaf(tb2.x, srow[q], scb[q]));
        float oy = fmaf(tw2.y, ay, fmaf(tb2.y, srow[q], scb[q]));
        *(float2*)(out + ((b*PP + q)*NN + n)*HH + h) = make_float2(ox, oy);
    }
}

// --------------------------------------------------------------------------
extern "C" void kernel_launch(void* const* d_in, const int* in_sizes, int n_in,
                              void* d_out, int out_size) {
    const float* x  = (const float*)d_in[0];
    const void*  ei = d_in[1];
    const float* gw = (const float*)d_in[2];
    const float* gb = (const float*)d_in[3];
    const float* tw = (const float*)d_in[4];
    const float* tb = (const float*)d_in[5];
    const float* cw = (const float*)d_in[6];
    const float* cb = (const float*)d_in[7];
    float* out = (float*)d_out;

    k_detect  <<<1, 32>>>(ei);
    k_zero    <<<8, 256>>>();
    k_count   <<<64, 256>>>(ei);
    k_scan    <<<1, 1024>>>();
    k_scatter <<<64, 256>>>(ei);
    k_sortfill<<<8, 256>>>(ei);
    k_stats1  <<<dim3(4, BPc), 256>>>((const float4*)x);
    k_stats1b <<<1, 256>>>();
    k_conv    <<<dim3(NN/8, BPc), 256>>>(x, gw, gb);
    k_stats2  <<<BPc, 256>>>();
    k_out     <<<4096, 256>>>(tw, tb, cw, cb, out);
}